// round 12
// baseline (speedup 1.0000x reference)
#include <cuda_runtime.h>
#include <stdint.h>

// GreedyGroupedRouter: SEQ=524288 tokens, 256 experts, 8 groups of 32, top-1/group.
// d_out layout (float32): rw[SEQ*256] | tw[SEQ*8] | tids[SEQ*8] | hist[256]
//
// Best-of-both: R11's in-loop shape (single 8-lane spread ATOMS per row ->
// ncu 179.2us, DRAM 74.6%) + R10's finalization (block-0 zero + flag, direct
// per-block float-atomic flush -> bench-ncu gap 1.2us). Grid = 1216 = 152 SMs
// x 8 blocks, one full wave, single graph node.

#define SEQ     524288
#define NE      256
#define NG      8
#define GS      32
#define TOPK    8

__device__ unsigned g_hist_ready = 0;
__device__ unsigned g_done_blocks = 0;

__global__ void __launch_bounds__(256)
router_kernel(const float* __restrict__ logits,
              float* __restrict__ rw,     // [SEQ, 256]
              float* __restrict__ tw,     // [SEQ, 8]
              float* __restrict__ tids,   // [SEQ, 8]
              float* __restrict__ hist)   // [256]
{
    __shared__ unsigned int shist[NE];
    for (int i = threadIdx.x; i < NE; i += blockDim.x) shist[i] = 0u;

    // Block 0 zeroes the global histogram, then publishes.
    if (blockIdx.x == 0) {
        hist[threadIdx.x] = 0.0f;         // blockDim.x == NE == 256
        __syncthreads();
        if (threadIdx.x == 0) {
            __threadfence();
            atomicExch(&g_hist_ready, 1u);
        }
    } else {
        __syncthreads();
    }

    const int lane   = threadIdx.x & 31;
    const int gwarp  = blockIdx.x * (blockDim.x >> 5) + (threadIdx.x >> 5);
    const int nwarps = gridDim.x * (blockDim.x >> 5);

    for (int row = gwarp; row < SEQ; row += nwarps) {
        const float* lp = logits + (size_t)row * NE;

        // Lane-strided: lane holds element (lane + 32*i); register i is this
        // lane's member of expert-group i. Each load is a coalesced 128B.
        float x[NG];
        #pragma unroll
        for (int i = 0; i < NG; i++) x[i] = lp[lane + GS * i];

        // Row max (softmax stabilization)
        float m = x[0];
        #pragma unroll
        for (int i = 1; i < NG; i++) m = fmaxf(m, x[i]);
        #pragma unroll
        for (int o = 16; o > 0; o >>= 1)
            m = fmaxf(m, __shfl_xor_sync(0xffffffffu, m, o));

        // exp + row sum
        float e[NG];
        float s = 0.0f;
        #pragma unroll
        for (int i = 0; i < NG; i++) { e[i] = __expf(x[i] - m); s += e[i]; }
        #pragma unroll
        for (int o = 16; o > 0; o >>= 1)
            s += __shfl_xor_sync(0xffffffffu, s, o);
        const float inv = 1.0f / s;

        // Softmax weights + immediate streaming store of routing_weights
        float* rp = rw + (size_t)row * NE;
        float w[NG];
        #pragma unroll
        for (int i = 0; i < NG; i++) {
            w[i] = e[i] * inv;
            rp[lane + GS * i] = w[i];
        }

        // Per-group argmax (group g = lanes' w[g]); tie-break to lowest index,
        // matching lax.top_k. Softmax values in (0,1] -> float bits monotone.
        float myw  = 0.0f;   // valid on lanes 0..7
        int   myid = 0;
        float sw   = 0.0f;
        #pragma unroll
        for (int g = 0; g < NG; g++) {
            unsigned u    = __float_as_uint(w[g]);
            unsigned umax = __reduce_max_sync(0xffffffffu, u);
            unsigned bal  = __ballot_sync(0xffffffffu, u == umax);
            int src       = __ffs(bal) - 1;           // lowest winning lane
            float gv      = __uint_as_float(umax);
            sw += gv;
            if (lane == g) { myw = gv; myid = g * GS + src; }
        }
        const float invsw = 1.0f / (sw + 1e-20f);

        if (lane < TOPK) {
            tw[(size_t)row * TOPK + lane]   = myw * invsw;
            tids[(size_t)row * TOPK + lane] = (float)myid;
            atomicAdd(&shist[myid], 1u);   // one 8-lane spread ATOMS per row
        }
    }

    __syncthreads();

    // Flush: wait (already set in practice) for hist to be zeroed.
    if (threadIdx.x == 0) {
        while (atomicAdd(&g_hist_ready, 0u) == 0u) __nanosleep(64);
        __threadfence();
    }
    __syncthreads();

    for (int i = threadIdx.x; i < NE; i += blockDim.x) {
        unsigned c = shist[i];
        if (c) atomicAdd(&hist[i], (float)c);
    }

    __syncthreads();
    if (threadIdx.x == 0) {
        __threadfence();
        unsigned d = atomicAdd(&g_done_blocks, 1u);
        if (d == gridDim.x - 1) {           // last block resets for next replay
            atomicExch(&g_done_blocks, 0u);
            atomicExch(&g_hist_ready, 0u);
        }
    }
}

extern "C" void kernel_launch(void* const* d_in, const int* in_sizes, int n_in,
                              void* d_out, int out_size) {
    const float* logits = (const float*)d_in[0];
    float* out  = (float*)d_out;
    float* rw   = out;
    float* tw   = rw   + (size_t)SEQ * NE;
    float* tids = tw   + (size_t)SEQ * TOPK;
    float* hist = tids + (size_t)SEQ * TOPK;

    // One full wave on GB300: 152 SMs x 8 blocks = 1216 (64 warps/SM).
    router_kernel<<<1216, 256>>>(logits, rw, tw, tids, hist);
}

// round 13
// speedup vs baseline: 1.0773x; 1.0773x over previous
#include <cuda_runtime.h>
#include <stdint.h>

// GreedyGroupedRouter: SEQ=524288 tokens, 256 experts, 8 groups of 32, top-1/group.
// d_out layout (float32): rw[SEQ*256] | tw[SEQ*8] | tids[SEQ*8] | hist[256]
//
// R11 inner loop verbatim (best measured: ncu 179.2us, DRAM 74.6%, regs 32,
// occ 91%) in the clean two-node structure (R1: bench-ncu gap 4.0us). No
// device flags, no spin, no completion counter — those cost regs/occ in R12.
// launch_bounds(256,8) pins regs <= 32.

#define SEQ     524288
#define NE      256
#define NG      8
#define GS      32
#define TOPK    8

__global__ void zero_hist_kernel(float* hist) {
    hist[threadIdx.x] = 0.0f;
}

__global__ void __launch_bounds__(256, 8)
router_kernel(const float* __restrict__ logits,
              float* __restrict__ rw,     // [SEQ, 256]
              float* __restrict__ tw,     // [SEQ, 8]
              float* __restrict__ tids,   // [SEQ, 8]
              float* __restrict__ hist)   // [256]
{
    __shared__ unsigned int shist[NE];
    for (int i = threadIdx.x; i < NE; i += blockDim.x) shist[i] = 0u;
    __syncthreads();

    const int lane   = threadIdx.x & 31;
    const int gwarp  = blockIdx.x * (blockDim.x >> 5) + (threadIdx.x >> 5);
    const int nwarps = gridDim.x * (blockDim.x >> 5);

    for (int row = gwarp; row < SEQ; row += nwarps) {
        const float* lp = logits + (size_t)row * NE;

        // Lane-strided: lane holds element (lane + 32*i); register i is this
        // lane's member of expert-group i. Each load is a coalesced 128B.
        float x[NG];
        #pragma unroll
        for (int i = 0; i < NG; i++) x[i] = lp[lane + GS * i];

        // Row max (softmax stabilization)
        float m = x[0];
        #pragma unroll
        for (int i = 1; i < NG; i++) m = fmaxf(m, x[i]);
        #pragma unroll
        for (int o = 16; o > 0; o >>= 1)
            m = fmaxf(m, __shfl_xor_sync(0xffffffffu, m, o));

        // exp + row sum
        float e[NG];
        float s = 0.0f;
        #pragma unroll
        for (int i = 0; i < NG; i++) { e[i] = __expf(x[i] - m); s += e[i]; }
        #pragma unroll
        for (int o = 16; o > 0; o >>= 1)
            s += __shfl_xor_sync(0xffffffffu, s, o);
        const float inv = 1.0f / s;

        // Softmax weights + immediate streaming store of routing_weights
        float* rp = rw + (size_t)row * NE;
        float w[NG];
        #pragma unroll
        for (int i = 0; i < NG; i++) {
            w[i] = e[i] * inv;
            rp[lane + GS * i] = w[i];
        }

        // Per-group argmax (group g = lanes' w[g]); tie-break to lowest index,
        // matching lax.top_k. Softmax values in (0,1] -> float bits monotone.
        float myw  = 0.0f;   // valid on lanes 0..7
        int   myid = 0;
        float sw   = 0.0f;
        #pragma unroll
        for (int g = 0; g < NG; g++) {
            unsigned u    = __float_as_uint(w[g]);
            unsigned umax = __reduce_max_sync(0xffffffffu, u);
            unsigned bal  = __ballot_sync(0xffffffffu, u == umax);
            int src       = __ffs(bal) - 1;           // lowest winning lane
            float gv      = __uint_as_float(umax);
            sw += gv;
            if (lane == g) { myw = gv; myid = g * GS + src; }
        }
        const float invsw = 1.0f / (sw + 1e-20f);

        if (lane < TOPK) {
            tw[(size_t)row * TOPK + lane]   = myw * invsw;
            tids[(size_t)row * TOPK + lane] = (float)myid;
            atomicAdd(&shist[myid], 1u);   // one 8-lane spread ATOMS per row
        }
    }

    __syncthreads();
    for (int i = threadIdx.x; i < NE; i += blockDim.x) {
        unsigned c = shist[i];
        if (c) atomicAdd(&hist[i], (float)c);
    }
}

extern "C" void kernel_launch(void* const* d_in, const int* in_sizes, int n_in,
                              void* d_out, int out_size) {
    const float* logits = (const float*)d_in[0];
    float* out  = (float*)d_out;
    float* rw   = out;
    float* tw   = rw   + (size_t)SEQ * NE;
    float* tids = tw   + (size_t)SEQ * TOPK;
    float* hist = tids + (size_t)SEQ * TOPK;

    zero_hist_kernel<<<1, NE>>>(hist);
    // One full wave on GB300: 152 SMs x 8 blocks = 1216 (64 warps/SM).
    router_kernel<<<1216, 256>>>(logits, rw, tw, tids, hist);
}

// round 14
// speedup vs baseline: 1.0843x; 1.0065x over previous
#include <cuda_runtime.h>
#include <stdint.h>

// GreedyGroupedRouter: SEQ=524288 tokens, 256 experts, 8 groups of 32, top-1/group.
// d_out layout (float32): rw[SEQ*256] | tw[SEQ*8] | tids[SEQ*8] | hist[256]
//
// R13 verbatim resubmission — best measured kernel (ncu 174.5us, DRAM 76.7%,
// 6076 GB/s, regs 32, occ 90%). R13's bench (198.4) ran in a slow-clock
// session (implied 5.4 TB/s vs ncu's 6.1 TB/s on identical code); bench-ncu
// gaps across rounds correlate with session, not structure. Re-sampling.
//
// Structure: two-node graph (zero_hist + router). Router: one warp per row,
// lane-strided scalar loads/stores (coalesced 128B), shfl row-max + row-sum,
// REDUX per-group argmax with lowest-index tie-break, one 8-lane spread
// shared-atomic histogram update per row, per-block float-atomic flush.

#define SEQ     524288
#define NE      256
#define NG      8
#define GS      32
#define TOPK    8

__global__ void zero_hist_kernel(float* hist) {
    hist[threadIdx.x] = 0.0f;
}

__global__ void __launch_bounds__(256, 8)
router_kernel(const float* __restrict__ logits,
              float* __restrict__ rw,     // [SEQ, 256]
              float* __restrict__ tw,     // [SEQ, 8]
              float* __restrict__ tids,   // [SEQ, 8]
              float* __restrict__ hist)   // [256]
{
    __shared__ unsigned int shist[NE];
    for (int i = threadIdx.x; i < NE; i += blockDim.x) shist[i] = 0u;
    __syncthreads();

    const int lane   = threadIdx.x & 31;
    const int gwarp  = blockIdx.x * (blockDim.x >> 5) + (threadIdx.x >> 5);
    const int nwarps = gridDim.x * (blockDim.x >> 5);

    for (int row = gwarp; row < SEQ; row += nwarps) {
        const float* lp = logits + (size_t)row * NE;

        // Lane-strided: lane holds element (lane + 32*i); register i is this
        // lane's member of expert-group i. Each load is a coalesced 128B.
        float x[NG];
        #pragma unroll
        for (int i = 0; i < NG; i++) x[i] = lp[lane + GS * i];

        // Row max (softmax stabilization)
        float m = x[0];
        #pragma unroll
        for (int i = 1; i < NG; i++) m = fmaxf(m, x[i]);
        #pragma unroll
        for (int o = 16; o > 0; o >>= 1)
            m = fmaxf(m, __shfl_xor_sync(0xffffffffu, m, o));

        // exp + row sum
        float e[NG];
        float s = 0.0f;
        #pragma unroll
        for (int i = 0; i < NG; i++) { e[i] = __expf(x[i] - m); s += e[i]; }
        #pragma unroll
        for (int o = 16; o > 0; o >>= 1)
            s += __shfl_xor_sync(0xffffffffu, s, o);
        const float inv = 1.0f / s;

        // Softmax weights + immediate streaming store of routing_weights
        float* rp = rw + (size_t)row * NE;
        float w[NG];
        #pragma unroll
        for (int i = 0; i < NG; i++) {
            w[i] = e[i] * inv;
            rp[lane + GS * i] = w[i];
        }

        // Per-group argmax (group g = lanes' w[g]); tie-break to lowest index,
        // matching lax.top_k. Softmax values in (0,1] -> float bits monotone.
        float myw  = 0.0f;   // valid on lanes 0..7
        int   myid = 0;
        float sw   = 0.0f;
        #pragma unroll
        for (int g = 0; g < NG; g++) {
            unsigned u    = __float_as_uint(w[g]);
            unsigned umax = __reduce_max_sync(0xffffffffu, u);
            unsigned bal  = __ballot_sync(0xffffffffu, u == umax);
            int src       = __ffs(bal) - 1;           // lowest winning lane
            float gv      = __uint_as_float(umax);
            sw += gv;
            if (lane == g) { myw = gv; myid = g * GS + src; }
        }
        const float invsw = 1.0f / (sw + 1e-20f);

        if (lane < TOPK) {
            tw[(size_t)row * TOPK + lane]   = myw * invsw;
            tids[(size_t)row * TOPK + lane] = (float)myid;
            atomicAdd(&shist[myid], 1u);   // one 8-lane spread ATOMS per row
        }
    }

    __syncthreads();
    for (int i = threadIdx.x; i < NE; i += blockDim.x) {
        unsigned c = shist[i];
        if (c) atomicAdd(&hist[i], (float)c);
    }
}

extern "C" void kernel_launch(void* const* d_in, const int* in_sizes, int n_in,
                              void* d_out, int out_size) {
    const float* logits = (const float*)d_in[0];
    float* out  = (float*)d_out;
    float* rw   = out;
    float* tw   = rw   + (size_t)SEQ * NE;
    float* tids = tw   + (size_t)SEQ * TOPK;
    float* hist = tids + (size_t)SEQ * TOPK;

    zero_hist_kernel<<<1, NE>>>(hist);
    // One full wave on GB300: 152 SMs x 8 blocks = 1216 (64 warps/SM).
    router_kernel<<<1216, 256>>>(logits, rw, tw, tids, hist);
}

// round 15
// speedup vs baseline: 1.1464x; 1.0573x over previous
#include <cuda_runtime.h>
#include <stdint.h>

// GreedyGroupedRouter: SEQ=524288 tokens, 256 experts, 8 groups of 32, top-1 per group.
// Outputs (all float32, concatenated in d_out):
//   [0)                routing_weights  SEQ*256
//   [SEQ*256)          topk_weights     SEQ*8
//   [SEQ*264)          topk_ids         SEQ*8   (integer values stored as float)
//   [SEQ*272)          tokens_per_expert 256
//
// Verbatim R1 resubmission — the sustained-bench champion (186.0 / 187.1 /
// 186.4 us across three sessions; every structural deviation measured >=197
// under the timed replay loop despite some showing better single-launch ncu
// durations). One warp per row, lane-strided scalar loads/stores (each a
// coalesced 128B access), shfl row-max + row-sum, REDUX per-group argmax with
// lowest-index tie-break, in-loop predicated shared-atomic histogram,
// per-block float-atomic flush.

#define SEQ     524288
#define NE      256
#define NG      8
#define GS      32
#define TOPK    8

__global__ void zero_hist_kernel(float* hist) {
    hist[threadIdx.x] = 0.0f;
}

__global__ void __launch_bounds__(256)
router_kernel(const float* __restrict__ logits,
              float* __restrict__ rw,     // [SEQ, 256]
              float* __restrict__ tw,     // [SEQ, 8]
              float* __restrict__ tids,   // [SEQ, 8]
              float* __restrict__ hist)   // [256]
{
    __shared__ unsigned int shist[NE];
    for (int i = threadIdx.x; i < NE; i += blockDim.x) shist[i] = 0u;
    __syncthreads();

    const int lane     = threadIdx.x & 31;
    const int warp_ib  = threadIdx.x >> 5;
    const int wpb      = blockDim.x >> 5;
    const int gwarp    = blockIdx.x * wpb + warp_ib;
    const int nwarps   = gridDim.x * wpb;

    for (int row = gwarp; row < SEQ; row += nwarps) {
        const float* lp = logits + (size_t)row * NE;

        // Lane-strided load: lane holds elements (lane + 32*i) -> element i is
        // this lane's member of expert-group i. Each load is a coalesced 128B.
        float x[NG];
        #pragma unroll
        for (int i = 0; i < NG; i++) x[i] = lp[lane + GS * i];

        // Row max (softmax stabilization)
        float m = x[0];
        #pragma unroll
        for (int i = 1; i < NG; i++) m = fmaxf(m, x[i]);
        #pragma unroll
        for (int o = 16; o > 0; o >>= 1)
            m = fmaxf(m, __shfl_xor_sync(0xffffffffu, m, o));

        // exp + row sum
        float e[NG];
        float s = 0.0f;
        #pragma unroll
        for (int i = 0; i < NG; i++) { e[i] = __expf(x[i] - m); s += e[i]; }
        #pragma unroll
        for (int o = 16; o > 0; o >>= 1)
            s += __shfl_xor_sync(0xffffffffu, s, o);
        const float inv = 1.0f / s;

        // Softmax weights + streaming store of routing_weights
        float* rp = rw + (size_t)row * NE;
        float w[NG];
        #pragma unroll
        for (int i = 0; i < NG; i++) {
            w[i] = e[i] * inv;
            rp[lane + GS * i] = w[i];
        }

        // Per-group argmax (group g = lanes' w[g]); tie-break to lowest lane
        // index, matching lax.top_k. Softmax values are in (0,1], so the
        // float bit pattern is monotone as unsigned.
        float myw  = 0.0f;   // valid on lanes 0..7
        float myid = 0.0f;
        float sw   = 0.0f;
        #pragma unroll
        for (int g = 0; g < NG; g++) {
            unsigned u    = __float_as_uint(w[g]);
            unsigned umax = __reduce_max_sync(0xffffffffu, u);
            unsigned bal  = __ballot_sync(0xffffffffu, u == umax);
            int src       = __ffs(bal) - 1;           // lowest winning lane
            float gv      = __uint_as_float(umax);
            sw += gv;
            if (lane == g) { myw = gv; myid = (float)(g * GS + src); }
            if (lane == src) atomicAdd(&shist[g * GS + src], 1u);
        }
        const float invsw = 1.0f / (sw + 1e-20f);

        if (lane < TOPK) {
            tw[(size_t)row * TOPK + lane]   = myw * invsw;
            tids[(size_t)row * TOPK + lane] = myid;
        }
    }

    __syncthreads();
    for (int i = threadIdx.x; i < NE; i += blockDim.x) {
        unsigned c = shist[i];
        if (c) atomicAdd(&hist[i], (float)c);
    }
}

extern "C" void kernel_launch(void* const* d_in, const int* in_sizes, int n_in,
                              void* d_out, int out_size) {
    const float* logits = (const float*)d_in[0];
    float* out  = (float*)d_out;
    float* rw   = out;
    float* tw   = rw   + (size_t)SEQ * NE;
    float* tids = tw   + (size_t)SEQ * TOPK;
    float* hist = tids + (size_t)SEQ * TOPK;

    zero_hist_kernel<<<1, NE>>>(hist);
    // 1184 blocks x 256 threads = 9472 warps, ~55 rows/warp grid-stride.
    router_kernel<<<1184, 256>>>(logits, rw, tw, tids, hist);
}